// round 8
// baseline (speedup 1.0000x reference)
#include <cuda_runtime.h>
#include <cuda_bf16.h>
#include <cstdint>

// ---------------- problem constants ----------------
#define NB     65536
#define GS     7
#define INH    5
#define GH     144
#define LINH   128
#define GPC    4              // graphs per CTA (padded to 8 rows each)
#define NCTA   (NB/GPC)       // 16384
#define NTHR   128            // 4 warps: (mtile 0..1) x (slot 0..1)
#define KT     9              // 144/16 k-tiles
#define NT     18             // 144/8 n-tiles (full N per warp)
#define HS2    290            // sH row stride (floats)
#define BBLK   512            // bytes per (ktile,ntile) B frag block
#define BSLOT  (KT*NT*BBLK)   // 82944 bytes per weight slot

// ---------------- device scratch ----------------
__device__ unsigned char g_B[4*BSLOT];   // frag-packed split-bf16 weights
__device__ float g_v[GH];                // fused fc vector

// ---------------- helpers ----------------
__device__ __forceinline__ uint32_t pack_bf16(float a, float b) {
    __nv_bfloat162 t = __floats2bfloat162_rn(a, b);
    return *(uint32_t*)&t;
}
__device__ __forceinline__ void hilo(float x, float& hi, float& lo) {
    hi = __bfloat162float(__float2bfloat16(x));
    lo = x - hi;
}
__device__ __forceinline__ void mma_bf16(float* c, uint32_t a0, uint32_t a1,
                                         uint32_t a2, uint32_t a3,
                                         uint32_t b0, uint32_t b1) {
    asm volatile(
        "mma.sync.aligned.m16n8k16.row.col.f32.bf16.bf16.f32 "
        "{%0,%1,%2,%3}, {%4,%5,%6,%7}, {%8,%9}, {%0,%1,%2,%3};"
        : "+f"(c[0]), "+f"(c[1]), "+f"(c[2]), "+f"(c[3])
        : "r"(a0), "r"(a1), "r"(a2), "r"(a3), "r"(b0), "r"(b1));
}
__device__ __forceinline__ uint32_t smem_u32(const void* p) {
    uint32_t a;
    asm("{ .reg .u64 t; cvta.to.shared.u64 t, %1; cvt.u32.u64 %0, t; }" : "=r"(a) : "l"(p));
    return a;
}
__device__ __forceinline__ void cp16(uint32_t dst, const void* src) {
    asm volatile("cp.async.cg.shared.global [%0], [%1], 16;" :: "r"(dst), "l"(src));
}

// ---------------- shared memory ----------------
struct SM {
    union {
        struct { uint4 sX[2*KT*64]; uint4 stage[2*NT*32]; } g;  // 18432 + 18432
        struct { float ops[GPC*35]; float w0[2*720]; } l0;
    } u;
    float h[32*HS2];            // 37120 B: 32 rows x [h1(144) | h2(144)] fp32
    float adjn[GPC*49];
    float adji[GPC*49];
    float adjraw[GPC*49];
    float v[GH];
    float gsum[GPC];
};
#define SMEMB ((int)sizeof(SM))   // ~76928 B -> 3 CTAs/SM

// ================= kernel: v = fc1^T fc2 ======================================
__global__ void k_v(const float* __restrict__ fc1, const float* __restrict__ fc2) {
    const int k = threadIdx.x;
    if (k < GH) {
        float s = 0.f;
        for (int j = 0; j < LINH; j++) s = fmaf(fc2[j], fc1[j*GH + k], s);
        g_v[k] = s;
    }
}

// ================= kernel: pack weights into B fragments ======================
// slot order: 0=w1_1 1=w2_1 2=w1_2 3=w2_2.
__global__ void k_bprep(const float* __restrict__ a, const float* __restrict__ b,
                        const float* __restrict__ c, const float* __restrict__ d) {
    const float* W = blockIdx.x == 0 ? a : blockIdx.x == 1 ? b
                   : blockIdx.x == 2 ? c : d;
    unsigned char* out = g_B + (size_t)blockIdx.x * BSLOT;
    for (int f = threadIdx.x; f < KT*NT*32; f += 256) {
        const int kt = f / (NT*32);
        const int nt = (f / 32) % NT;
        const int l  = f & 31;
        const int n  = nt*8 + (l >> 2);
        const int kb = kt*16 + (l & 3)*2;
        float w0 = W[(kb+0)*GH + n], w1 = W[(kb+1)*GH + n];
        float w8 = W[(kb+8)*GH + n], w9 = W[(kb+9)*GH + n];
        float h0,l0,h1,l1,h8,l8,h9,l9;
        hilo(w0,h0,l0); hilo(w1,h1,l1); hilo(w8,h8,l8); hilo(w9,h9,l9);
        uint4 v;
        v.x = pack_bf16(h0,h1); v.y = pack_bf16(h8,h9);
        v.z = pack_bf16(l0,l1); v.w = pack_bf16(l8,l9);
        *(uint4*)(out + (size_t)(kt*NT + nt)*BBLK + l*16) = v;
    }
}

// ================= per-graph adjacency prep ====================================
__device__ void prep_graph(SM* s, int g) {
    float a[49];
#pragma unroll
    for (int i = 0; i < 49; i++) a[i] = s->adjraw[g*49 + i];
#pragma unroll
    for (int i = 0; i < 7; i++) {
        a[i*7 + i] += 1.0f;
        float rs = 0.f;
#pragma unroll
        for (int j = 0; j < 7; j++) rs += a[i*7 + j];
        const float inv = 1.0f / rs;
#pragma unroll
        for (int j = 0; j < 7; j++) a[i*7 + j] *= inv;
    }
#pragma unroll
    for (int i = 0; i < 7; i++) {
        float rs = 0.f;
#pragma unroll
        for (int j = 0; j < 7; j++) rs += a[i*7 + j];
        const float inv = 1.0f / rs;
#pragma unroll
        for (int j = 0; j < 7; j++) s->adjn[g*49 + i*7 + j] = a[i*7 + j] * inv;
    }
#pragma unroll
    for (int i = 0; i < 7; i++) {
        float cs = 0.f;
#pragma unroll
        for (int r = 0; r < 7; r++) cs += a[r*7 + i];
        const float inv = 1.0f / cs;
#pragma unroll
        for (int j = 0; j < 7; j++) s->adji[g*49 + i*7 + j] = a[j*7 + i] * inv;
    }
}

// ================= mix: sH -> (sX frags | pooled gsum) ========================
template <bool FINAL>
__device__ void mix(SM* s) {
    const int tid = threadIdx.x;
    __syncthreads();   // sH complete; all sX/stage reads done

    for (int item = tid; item < GPC*72; item += NTHR) {
        const int g  = item / 72;
        const int kp = item - g*72;
        const int k0 = kp*2;

        float h1a[7], h1b[7], h2a[7], h2b[7];
#pragma unroll
        for (int j = 0; j < 7; j++) {
            const float2 t1 = *(const float2*)&s->h[(g*8+j)*HS2 + k0];
            const float2 t2 = *(const float2*)&s->h[(g*8+j)*HS2 + GH + k0];
            h1a[j] = t1.x; h1b[j] = t1.y;
            h2a[j] = t2.x; h2b[j] = t2.y;
        }
        const float* an = &s->adjn[g*49];
        const float* ai = &s->adji[g*49];

        const int mt = g >> 1;
        const int kt = k0 >> 4, c2 = (k0 & 15) >> 1;
        uint32_t* X = (uint32_t*)s->u.g.sX;
        const int base = (mt*KT + kt)*256;
        const int wsel = (g & 1) + 2*(c2 >> 2);

        float cs0 = 0.f, cs1 = 0.f;
#pragma unroll
        for (int i = 0; i < 7; i++) {
            float o1a = 0.f, o1b = 0.f, o2a = 0.f, o2b = 0.f;
#pragma unroll
            for (int j = 0; j < 7; j++) {
                const float wn = an[i*7 + j], wi = ai[i*7 + j];
                o1a = fmaf(wn, h1a[j], o1a); o1b = fmaf(wn, h1b[j], o1b);
                o2a = fmaf(wi, h2a[j], o2a); o2b = fmaf(wi, h2b[j], o2b);
            }
            const float x0 = 0.5f * (fmaxf(o1a, 0.f) + fmaxf(o2a, 0.f));
            const float x1 = 0.5f * (fmaxf(o1b, 0.f) + fmaxf(o2b, 0.f));

            if (!FINAL) {
                float hi0, lo0, hi1, lo1;
                hilo(x0, hi0, lo0); hilo(x1, hi1, lo1);
                const int l = i*4 + (c2 & 3);
                X[base + l*4 + wsel]       = pack_bf16(hi0, hi1);
                X[base + 128 + l*4 + wsel] = pack_bf16(lo0, lo1);
            } else {
                cs0 += x0; cs1 += x1;
            }
        }
        if (FINAL)
            atomicAdd(&s->gsum[g], cs0 * s->v[k0] + cs1 * s->v[k0+1]);
    }
    __syncthreads();   // sX/gsum complete before next phase
}

// ================= GEMM with cooperative cp.async B staging ===================
__device__ void gemm(SM* s, int mt, int sl, int slot0, uint32_t stage_sa) {
    const int tid = threadIdx.x, lane = tid & 31;
    const uint4* __restrict__ B0 = (const uint4*)(g_B + (size_t)slot0*BSLOT);
    const uint4* __restrict__ B1 = B0 + BSLOT/16;
    const uint4* Xv = s->u.g.sX;
    const uint4* stg = s->u.g.stage;

    float acc[NT][4];
#pragma unroll
    for (int t = 0; t < NT; t++)
#pragma unroll
        for (int q = 0; q < 4; q++) acc[t][q] = 0.f;

#pragma unroll 1
    for (int kt = 0; kt < KT; kt++) {
        // stage both slots' (kt,*) blocks: 1152 uint4 = 18KB
#pragma unroll
        for (int i = 0; i < 9; i++) {
            const int idx = tid + i*NTHR;
            const uint4* src = (idx < 576) ? (B0 + kt*576 + idx)
                                           : (B1 + kt*576 + (idx - 576));
            cp16(stage_sa + idx*16, src);
        }
        asm volatile("cp.async.commit_group;" ::: "memory");
        asm volatile("cp.async.wait_group 0;" ::: "memory");
        __syncthreads();

        const uint4 ah = Xv[(mt*KT + kt)*64 + lane];
        const uint4 al = Xv[(mt*KT + kt)*64 + 32 + lane];
        const uint4* bw = stg + sl*576;
#pragma unroll
        for (int nt = 0; nt < NT; nt++) {
            const uint4 b = bw[nt*32 + lane];
            mma_bf16(acc[nt], ah.x, ah.y, ah.z, ah.w, b.x, b.y);  // hi*hi
            mma_bf16(acc[nt], ah.x, ah.y, ah.z, ah.w, b.z, b.w);  // hi*lo
            mma_bf16(acc[nt], al.x, al.y, al.z, al.w, b.x, b.y);  // lo*hi
        }
        __syncthreads();   // all warps done with stage before overwrite
    }

    const int r0 = mt*16 + (lane >> 2);
    const int c0 = sl*GH + (lane & 3)*2;
#pragma unroll
    for (int nt = 0; nt < NT; nt++) {
        *(float2*)&s->h[r0*HS2 + c0 + nt*8]     = make_float2(acc[nt][0], acc[nt][1]);
        *(float2*)&s->h[(r0+8)*HS2 + c0 + nt*8] = make_float2(acc[nt][2], acc[nt][3]);
    }
}

// ================= the fused kernel ===========================================
__global__ void __launch_bounds__(NTHR, 3)
k_fused(const float* __restrict__ ops, const float* __restrict__ adj,
        const float* __restrict__ nv,
        const float* __restrict__ w1_0, const float* __restrict__ w2_0,
        float* __restrict__ out) {
    extern __shared__ unsigned char smraw[];
    SM* s = (SM*)smraw;
    const int cta = blockIdx.x, tid = threadIdx.x;
    const int warp = tid >> 5, lane = tid & 31;
    const int mt = warp >> 1, sl = warp & 1;
    const uint32_t stage_sa = smem_u32(s->u.g.stage);

    // ---- cooperative loads ----
    for (int q = tid; q < GPC*35; q += NTHR) s->u.l0.ops[q] = ops[(size_t)cta*GPC*35 + q];
    for (int q = tid; q < 720; q += NTHR) {
        s->u.l0.w0[q]       = w1_0[q];
        s->u.l0.w0[720 + q] = w2_0[q];
    }
    for (int q = tid; q < GH; q += NTHR)     s->v[q] = g_v[q];
    for (int q = tid; q < GPC*49; q += NTHR) s->adjraw[q] = adj[(size_t)cta*GPC*49 + q];
    if (tid < GPC) s->gsum[tid] = 0.f;
    __syncthreads();

    // ---- adjacency prep ----
    if (tid < GPC) prep_graph(s, tid);

    // ---- layer 0: h = ops @ W (K=5) ----
    {
        const int r0 = lane >> 2;          // 0..7 (7 = pad row)
        const int g0 = 2*mt, g1 = 2*mt + 1;
        const float* W = &s->u.l0.w0[sl*720];
        float o0[INH], o1[INH];
#pragma unroll
        for (int t = 0; t < INH; t++) {
            o0[t] = (r0 < 7) ? s->u.l0.ops[g0*35 + r0*5 + t] : 0.f;
            o1[t] = (r0 < 7) ? s->u.l0.ops[g1*35 + r0*5 + t] : 0.f;
        }
        const int rr = mt*16 + r0;
        const int cb = sl*GH + (lane & 3)*2;
#pragma unroll
        for (int nt = 0; nt < NT; nt++) {
            const int c = nt*8 + (lane & 3)*2;
            float h00 = 0.f, h01 = 0.f, h10 = 0.f, h11 = 0.f;
#pragma unroll
            for (int t = 0; t < INH; t++) {
                const float wa = W[t*GH + c], wb = W[t*GH + c + 1];
                h00 = fmaf(o0[t], wa, h00); h01 = fmaf(o0[t], wb, h01);
                h10 = fmaf(o1[t], wa, h10); h11 = fmaf(o1[t], wb, h11);
            }
            *(float2*)&s->h[rr*HS2 + cb + nt*8]     = make_float2(h00, h01);
            *(float2*)&s->h[(rr+8)*HS2 + cb + nt*8] = make_float2(h10, h11);
        }
    }
    mix<false>(s);                      // L0 mix -> sX (X1 frags)

    gemm(s, mt, sl, 0, stage_sa);       // layer 1: slots {w1_1, w2_1}
    mix<false>(s);                      // -> sX (X2 frags)

    gemm(s, mt, sl, 2, stage_sa);       // layer 2: slots {w1_2, w2_2}
    mix<true>(s);                       // -> gsum (pool . v)

    if (tid < GPC) {
        const int b = cta*GPC + tid;
        out[b] = s->gsum[tid] / nv[b];
    }
}

// ================= launch ======================================================
extern "C" void kernel_launch(void* const* d_in, const int* in_sizes, int n_in,
                              void* d_out, int out_size) {
    const float* ops  = (const float*)d_in[0];
    const float* adj  = (const float*)d_in[1];
    const float* nv   = (const float*)d_in[2];
    const float* w1_0 = (const float*)d_in[3];
    const float* w2_0 = (const float*)d_in[4];
    const float* w1_1 = (const float*)d_in[5];
    const float* w2_1 = (const float*)d_in[6];
    const float* w1_2 = (const float*)d_in[7];
    const float* w2_2 = (const float*)d_in[8];
    const float* fc1  = (const float*)d_in[9];
    const float* fc2  = (const float*)d_in[10];
    float* out = (float*)d_out;

    static int configured = 0;
    if (!configured) {
        cudaFuncSetAttribute(k_fused, cudaFuncAttributeMaxDynamicSharedMemorySize, SMEMB);
        configured = 1;
    }

    k_v    <<<1, GH>>>(fc1, fc2);
    k_bprep<<<4, 256>>>(w1_1, w2_1, w1_2, w2_2);
    k_fused<<<NCTA, NTHR, SMEMB>>>(ops, adj, nv, w1_0, w2_0, out);
}

// round 9
// speedup vs baseline: 1.3311x; 1.3311x over previous
#include <cuda_runtime.h>
#include <cuda_bf16.h>
#include <cstdint>

// ---------------- problem constants ----------------
#define NB     65536
#define GS     7
#define INH    5
#define GH     144
#define LINH   128
#define GPC    8              // graphs per CTA (padded to 8 rows each) = 64 rows
#define NCTA   (NB/GPC)       // 8192
#define NTHR   128            // 4 warps: (mtile-pair 0..1) x (slot 0..1)
#define KT     9              // 144/16 k-tiles
#define NT     18             // 144/8 n-tiles (full N per warp)
#define HS2    290            // sH row stride (floats)
#define BBLK   512            // bytes per (ktile,ntile) B frag block
#define BSLOT  (KT*NT*BBLK)   // 82944 bytes per weight slot

// ---------------- device scratch ----------------
__device__ unsigned char g_B[4*BSLOT];   // frag-packed split-bf16 weights
__device__ float g_v[GH];                // fused fc vector

// ---------------- helpers ----------------
__device__ __forceinline__ uint32_t pack_bf16(float a, float b) {
    __nv_bfloat162 t = __floats2bfloat162_rn(a, b);
    return *(uint32_t*)&t;
}
__device__ __forceinline__ void hilo(float x, float& hi, float& lo) {
    hi = __bfloat162float(__float2bfloat16(x));
    lo = x - hi;
}
__device__ __forceinline__ void mma_bf16(float* c, uint32_t a0, uint32_t a1,
                                         uint32_t a2, uint32_t a3,
                                         uint32_t b0, uint32_t b1) {
    asm volatile(
        "mma.sync.aligned.m16n8k16.row.col.f32.bf16.bf16.f32 "
        "{%0,%1,%2,%3}, {%4,%5,%6,%7}, {%8,%9}, {%0,%1,%2,%3};"
        : "+f"(c[0]), "+f"(c[1]), "+f"(c[2]), "+f"(c[3])
        : "r"(a0), "r"(a1), "r"(a2), "r"(a3), "r"(b0), "r"(b1));
}

// ---------------- shared memory ----------------
struct SM {
    float h[64*HS2];            // 74240 B: 64 rows x [h1(144) | h2(144)] fp32
    union {
        uint4 sX[4*KT*64];      // 36864 B: frag-packed split-bf16 X (4 mtiles)
        struct {                // layer-0 scratch (consumed before sX written)
            float ops[GPC*35];
            float w0[2*720];
            float adjraw[GPC*49];
        } l0;
    } u;
    float adjn[GPC*49];
    float adji[GPC*49];
    float v[GH];
    float gsum[GPC];
};
#define SMEMB ((int)sizeof(SM))   // ~114.9 KB -> 2 CTAs/SM

// ================= kernel: v = fc1^T fc2 ======================================
__global__ void k_v(const float* __restrict__ fc1, const float* __restrict__ fc2) {
    const int k = threadIdx.x;
    if (k < GH) {
        float s = 0.f;
        for (int j = 0; j < LINH; j++) s = fmaf(fc2[j], fc1[j*GH + k], s);
        g_v[k] = s;
    }
}

// ================= kernel: pack weights into B fragments ======================
// slot order: 0=w1_1 1=w2_1 2=w1_2 3=w2_2.
__global__ void k_bprep(const float* __restrict__ a, const float* __restrict__ b,
                        const float* __restrict__ c, const float* __restrict__ d) {
    const float* W = blockIdx.x == 0 ? a : blockIdx.x == 1 ? b
                   : blockIdx.x == 2 ? c : d;
    unsigned char* out = g_B + (size_t)blockIdx.x * BSLOT;
    for (int f = threadIdx.x; f < KT*NT*32; f += 256) {
        const int kt = f / (NT*32);
        const int nt = (f / 32) % NT;
        const int l  = f & 31;
        const int n  = nt*8 + (l >> 2);
        const int kb = kt*16 + (l & 3)*2;
        float w0 = W[(kb+0)*GH + n], w1 = W[(kb+1)*GH + n];
        float w8 = W[(kb+8)*GH + n], w9 = W[(kb+9)*GH + n];
        float h0,l0,h1,l1,h8,l8,h9,l9;
        hilo(w0,h0,l0); hilo(w1,h1,l1); hilo(w8,h8,l8); hilo(w9,h9,l9);
        uint4 v;
        v.x = pack_bf16(h0,h1); v.y = pack_bf16(h8,h9);
        v.z = pack_bf16(l0,l1); v.w = pack_bf16(l8,l9);
        *(uint4*)(out + (size_t)(kt*NT + nt)*BBLK + l*16) = v;
    }
}

// ================= per-graph adjacency prep ====================================
__device__ void prep_graph(SM* s, int g) {
    float a[49];
#pragma unroll
    for (int i = 0; i < 49; i++) a[i] = s->u.l0.adjraw[g*49 + i];
#pragma unroll
    for (int i = 0; i < 7; i++) {
        a[i*7 + i] += 1.0f;
        float rs = 0.f;
#pragma unroll
        for (int j = 0; j < 7; j++) rs += a[i*7 + j];
        const float inv = 1.0f / rs;
#pragma unroll
        for (int j = 0; j < 7; j++) a[i*7 + j] *= inv;
    }
#pragma unroll
    for (int i = 0; i < 7; i++) {
        float rs = 0.f;
#pragma unroll
        for (int j = 0; j < 7; j++) rs += a[i*7 + j];
        const float inv = 1.0f / rs;
#pragma unroll
        for (int j = 0; j < 7; j++) s->adjn[g*49 + i*7 + j] = a[i*7 + j] * inv;
    }
#pragma unroll
    for (int i = 0; i < 7; i++) {
        float cs = 0.f;
#pragma unroll
        for (int r = 0; r < 7; r++) cs += a[r*7 + i];
        const float inv = 1.0f / cs;
#pragma unroll
        for (int j = 0; j < 7; j++) s->adji[g*49 + i*7 + j] = a[j*7 + i] * inv;
    }
}

// ================= mix: sH -> (sX frags | pooled gsum) ========================
template <bool FINAL>
__device__ void mix(SM* s) {
    const int tid = threadIdx.x;
    __syncthreads();   // sH complete; prior sX reads done

    for (int item = tid; item < GPC*72; item += NTHR) {
        const int g  = item / 72;
        const int kp = item - g*72;
        const int k0 = kp*2;

        float h1a[7], h1b[7], h2a[7], h2b[7];
#pragma unroll
        for (int j = 0; j < 7; j++) {
            const float2 t1 = *(const float2*)&s->h[(g*8+j)*HS2 + k0];
            const float2 t2 = *(const float2*)&s->h[(g*8+j)*HS2 + GH + k0];
            h1a[j] = t1.x; h1b[j] = t1.y;
            h2a[j] = t2.x; h2b[j] = t2.y;
        }
        const float* an = &s->adjn[g*49];
        const float* ai = &s->adji[g*49];

        const int mt = g >> 1;                 // 0..3
        const int kt = k0 >> 4, c2 = (k0 & 15) >> 1;
        uint32_t* X = (uint32_t*)s->u.sX;
        const int base = (mt*KT + kt)*256;
        const int wsel = (g & 1) + 2*(c2 >> 2);

        float cs0 = 0.f, cs1 = 0.f;
#pragma unroll
        for (int i = 0; i < 7; i++) {
            float o1a = 0.f, o1b = 0.f, o2a = 0.f, o2b = 0.f;
#pragma unroll
            for (int j = 0; j < 7; j++) {
                const float wn = an[i*7 + j], wi = ai[i*7 + j];
                o1a = fmaf(wn, h1a[j], o1a); o1b = fmaf(wn, h1b[j], o1b);
                o2a = fmaf(wi, h2a[j], o2a); o2b = fmaf(wi, h2b[j], o2b);
            }
            const float x0 = 0.5f * (fmaxf(o1a, 0.f) + fmaxf(o2a, 0.f));
            const float x1 = 0.5f * (fmaxf(o1b, 0.f) + fmaxf(o2b, 0.f));

            if (!FINAL) {
                float hi0, lo0, hi1, lo1;
                hilo(x0, hi0, lo0); hilo(x1, hi1, lo1);
                const int l = i*4 + (c2 & 3);
                X[base + l*4 + wsel]       = pack_bf16(hi0, hi1);
                X[base + 128 + l*4 + wsel] = pack_bf16(lo0, lo1);
            } else {
                cs0 += x0; cs1 += x1;
            }
        }
        if (FINAL)
            atomicAdd(&s->gsum[g], cs0 * s->v[k0] + cs1 * s->v[k0+1]);
    }
    __syncthreads();   // sX/gsum complete before next phase
}

// ================= GEMM: 2 mtiles per warp, B loaded once per 6 mma ==========
__device__ void gemm(SM* s, int mtp, int sl, int slot) {
    const int lane = threadIdx.x & 31;
    const uint4* __restrict__ Bp = (const uint4*)(g_B + (size_t)slot*BSLOT);
    const uint4* Xv = s->u.sX;
    const int m0 = 2*mtp, m1 = 2*mtp + 1;

    float acc[2][NT][4];
#pragma unroll
    for (int m = 0; m < 2; m++)
#pragma unroll
        for (int t = 0; t < NT; t++)
#pragma unroll
            for (int q = 0; q < 4; q++) acc[m][t][q] = 0.f;

#pragma unroll 1
    for (int kt = 0; kt < KT; kt++) {
        const uint4 a0h = Xv[(m0*KT + kt)*64 + lane];
        const uint4 a0l = Xv[(m0*KT + kt)*64 + 32 + lane];
        const uint4 a1h = Xv[(m1*KT + kt)*64 + lane];
        const uint4 a1l = Xv[(m1*KT + kt)*64 + 32 + lane];
#pragma unroll
        for (int nt = 0; nt < NT; nt++) {
            const uint4 b = Bp[(kt*NT + nt)*32 + lane];
            mma_bf16(acc[0][nt], a0h.x, a0h.y, a0h.z, a0h.w, b.x, b.y);
            mma_bf16(acc[0][nt], a0h.x, a0h.y, a0h.z, a0h.w, b.z, b.w);
            mma_bf16(acc[0][nt], a0l.x, a0l.y, a0l.z, a0l.w, b.x, b.y);
            mma_bf16(acc[1][nt], a1h.x, a1h.y, a1h.z, a1h.w, b.x, b.y);
            mma_bf16(acc[1][nt], a1h.x, a1h.y, a1h.z, a1h.w, b.z, b.w);
            mma_bf16(acc[1][nt], a1l.x, a1l.y, a1l.z, a1l.w, b.x, b.y);
        }
    }

    const int c0 = sl*GH + (lane & 3)*2;
#pragma unroll
    for (int m = 0; m < 2; m++) {
        const int r0 = (2*mtp + m)*16 + (lane >> 2);
#pragma unroll
        for (int nt = 0; nt < NT; nt++) {
            *(float2*)&s->h[r0*HS2 + c0 + nt*8]     = make_float2(acc[m][nt][0], acc[m][nt][1]);
            *(float2*)&s->h[(r0+8)*HS2 + c0 + nt*8] = make_float2(acc[m][nt][2], acc[m][nt][3]);
        }
    }
}

// ================= the fused kernel ===========================================
__global__ void __launch_bounds__(NTHR, 2)
k_fused(const float* __restrict__ ops, const float* __restrict__ adj,
        const float* __restrict__ nv,
        const float* __restrict__ w1_0, const float* __restrict__ w2_0,
        float* __restrict__ out) {
    extern __shared__ unsigned char smraw[];
    SM* s = (SM*)smraw;
    const int cta = blockIdx.x, tid = threadIdx.x;
    const int warp = tid >> 5, lane = tid & 31;
    const int mtp = warp >> 1, sl = warp & 1;

    // ---- cooperative loads ----
    for (int q = tid; q < GPC*35; q += NTHR) s->u.l0.ops[q] = ops[(size_t)cta*GPC*35 + q];
    for (int q = tid; q < 720; q += NTHR) {
        s->u.l0.w0[q]       = w1_0[q];
        s->u.l0.w0[720 + q] = w2_0[q];
    }
    for (int q = tid; q < GH; q += NTHR)     s->v[q] = g_v[q];
    for (int q = tid; q < GPC*49; q += NTHR) s->u.l0.adjraw[q] = adj[(size_t)cta*GPC*49 + q];
    if (tid < GPC) s->gsum[tid] = 0.f;
    __syncthreads();

    // ---- adjacency prep (one thread per graph) ----
    if (tid < GPC) prep_graph(s, tid);

    // ---- layer 0: h = ops @ W (K=5), 4 graphs per warp ----
    {
        const int r0 = lane >> 2;              // 0..7 (7 = pad row)
        const int cb = sl*GH + (lane & 3)*2;
        const float* W = &s->u.l0.w0[sl*720];
#pragma unroll
        for (int q = 0; q < 4; q++) {
            const int g = 4*mtp + q;
            float o[INH];
#pragma unroll
            for (int t = 0; t < INH; t++)
                o[t] = (r0 < 7) ? s->u.l0.ops[g*35 + r0*5 + t] : 0.f;
            const int rr = g*8 + r0;
#pragma unroll
            for (int nt = 0; nt < NT; nt++) {
                const int c = nt*8 + (lane & 3)*2;
                float ha = 0.f, hb = 0.f;
#pragma unroll
                for (int t = 0; t < INH; t++) {
                    ha = fmaf(o[t], W[t*GH + c],     ha);
                    hb = fmaf(o[t], W[t*GH + c + 1], hb);
                }
                *(float2*)&s->h[rr*HS2 + cb + nt*8] = make_float2(ha, hb);
            }
        }
    }
    mix<false>(s);              // L0 mix -> sX (X1 frags)

    gemm(s, mtp, sl, 0 + sl);   // layer 1: slots {w1_1, w2_1}
    mix<false>(s);              // -> sX (X2 frags)

    gemm(s, mtp, sl, 2 + sl);   // layer 2: slots {w1_2, w2_2}
    mix<true>(s);               // -> gsum (pool . v)

    if (tid < GPC) {
        const int b = cta*GPC + tid;
        out[b] = s->gsum[tid] / nv[b];
    }
}

// ================= launch ======================================================
extern "C" void kernel_launch(void* const* d_in, const int* in_sizes, int n_in,
                              void* d_out, int out_size) {
    const float* ops  = (const float*)d_in[0];
    const float* adj  = (const float*)d_in[1];
    const float* nv   = (const float*)d_in[2];
    const float* w1_0 = (const float*)d_in[3];
    const float* w2_0 = (const float*)d_in[4];
    const float* w1_1 = (const float*)d_in[5];
    const float* w2_1 = (const float*)d_in[6];
    const float* w1_2 = (const float*)d_in[7];
    const float* w2_2 = (const float*)d_in[8];
    const float* fc1  = (const float*)d_in[9];
    const float* fc2  = (const float*)d_in[10];
    float* out = (float*)d_out;

    static int configured = 0;
    if (!configured) {
        cudaFuncSetAttribute(k_fused, cudaFuncAttributeMaxDynamicSharedMemorySize, SMEMB);
        configured = 1;
    }

    k_v    <<<1, GH>>>(fc1, fc2);
    k_bprep<<<4, 256>>>(w1_1, w2_1, w1_2, w2_2);
    k_fused<<<NCTA, NTHR, SMEMB>>>(ops, adj, nv, w1_0, w2_0, out);
}

// round 10
// speedup vs baseline: 1.6375x; 1.2302x over previous
#include <cuda_runtime.h>
#include <cuda_fp16.h>
#include <cstdint>

// ---------------- problem constants ----------------
#define NB     65536
#define GS     7
#define INH    5
#define GH     144
#define LINH   128
#define GPC    4              // graphs per CTA (padded to 8 rows each)
#define NCTA   (NB/GPC)       // 16384
#define NTHR   128            // 4 warps: (mtile 0..1) x (slot 0..1)
#define KT     9              // 144/16 k-tiles
#define NT     18             // 144/8 n-tiles (full N per warp)
#define HS2    290            // sH row stride (floats)
#define BBLK   256            // bytes per (ktile,ntile) B frag block (hi only)
#define BSLOT  (KT*NT*BBLK)   // 41472 bytes per weight slot

// ---------------- device scratch ----------------
__device__ unsigned char g_B[4*BSLOT];   // frag-packed fp16(hi) weights
__device__ float g_v[GH];                // fused fc vector

// ---------------- helpers ----------------
__device__ __forceinline__ uint32_t pack_h(float a, float b) {
    __half2 t = __floats2half2_rn(a, b);   // a in low half
    return *(uint32_t*)&t;
}
__device__ __forceinline__ void hilo_h(float x, float& hi, float& lo) {
    hi = __half2float(__float2half(x));
    lo = x - hi;
}
__device__ __forceinline__ void mma_f16(float* c, uint32_t a0, uint32_t a1,
                                        uint32_t a2, uint32_t a3,
                                        uint32_t b0, uint32_t b1) {
    asm volatile(
        "mma.sync.aligned.m16n8k16.row.col.f32.f16.f16.f32 "
        "{%0,%1,%2,%3}, {%4,%5,%6,%7}, {%8,%9}, {%0,%1,%2,%3};"
        : "+f"(c[0]), "+f"(c[1]), "+f"(c[2]), "+f"(c[3])
        : "r"(a0), "r"(a1), "r"(a2), "r"(a3), "r"(b0), "r"(b1));
}

// ---------------- shared memory ----------------
struct SM {
    union {
        uint4 sX[2*KT*64];      // 18432 B: frag-packed fp16 hi|lo X (2 mtiles)
        struct { float ops[GPC*35]; float w0[2*720]; } l0;
    } u;
    float h[32*HS2];            // 37120 B: 32 rows x [h1(144) | h2(144)] fp32
    float adjn[GPC*49];
    float adji[GPC*49];
    float adjraw[GPC*49];
    float v[GH];
    float gsum[GPC];
};
#define SMEMB ((int)sizeof(SM))   // ~58 KB -> 3 CTAs/SM

// ================= single prep kernel: blocks 0-3 pack B, block 4 builds v ====
// slot order: 0=w1_1 1=w2_1 2=w1_2 3=w2_2.
__global__ void k_prep(const float* __restrict__ wa, const float* __restrict__ wb,
                       const float* __restrict__ wc, const float* __restrict__ wd,
                       const float* __restrict__ fc1, const float* __restrict__ fc2) {
    if (blockIdx.x == 4) {
        const int k = threadIdx.x;
        if (k < GH) {
            float s = 0.f;
            for (int j = 0; j < LINH; j++) s = fmaf(fc2[j], fc1[j*GH + k], s);
            g_v[k] = s;
        }
        return;
    }
    const float* W = blockIdx.x == 0 ? wa : blockIdx.x == 1 ? wb
                   : blockIdx.x == 2 ? wc : wd;
    unsigned char* out = g_B + (size_t)blockIdx.x * BSLOT;
    for (int f = threadIdx.x; f < KT*NT*32; f += 256) {
        const int kt = f / (NT*32);
        const int nt = (f / 32) % NT;
        const int l  = f & 31;
        const int n  = nt*8 + (l >> 2);
        const int kb = kt*16 + (l & 3)*2;
        uint2 v;
        v.x = pack_h(W[(kb+0)*GH + n], W[(kb+1)*GH + n]);
        v.y = pack_h(W[(kb+8)*GH + n], W[(kb+9)*GH + n]);
        *(uint2*)(out + (size_t)(kt*NT + nt)*BBLK + l*8) = v;
    }
}

// ================= per-graph adjacency prep ====================================
__device__ void prep_graph(SM* s, int g) {
    float a[49];
#pragma unroll
    for (int i = 0; i < 49; i++) a[i] = s->adjraw[g*49 + i];
#pragma unroll
    for (int i = 0; i < 7; i++) {
        a[i*7 + i] += 1.0f;
        float rs = 0.f;
#pragma unroll
        for (int j = 0; j < 7; j++) rs += a[i*7 + j];
        const float inv = 1.0f / rs;
#pragma unroll
        for (int j = 0; j < 7; j++) a[i*7 + j] *= inv;
    }
#pragma unroll
    for (int i = 0; i < 7; i++) {
        float rs = 0.f;
#pragma unroll
        for (int j = 0; j < 7; j++) rs += a[i*7 + j];
        const float inv = 1.0f / rs;
#pragma unroll
        for (int j = 0; j < 7; j++) s->adjn[g*49 + i*7 + j] = a[i*7 + j] * inv;
    }
#pragma unroll
    for (int i = 0; i < 7; i++) {
        float cs = 0.f;
#pragma unroll
        for (int r = 0; r < 7; r++) cs += a[r*7 + i];
        const float inv = 1.0f / cs;
#pragma unroll
        for (int j = 0; j < 7; j++) s->adji[g*49 + i*7 + j] = a[j*7 + i] * inv;
    }
}

// ================= mix: sH -> (sX frags | pooled gsum) ========================
template <bool FINAL>
__device__ void mix(SM* s) {
    const int tid = threadIdx.x;
    __syncthreads();   // sH complete; prior sX reads done

    for (int item = tid; item < GPC*72; item += NTHR) {
        const int g  = item / 72;
        const int kp = item - g*72;
        const int k0 = kp*2;

        float h1a[7], h1b[7], h2a[7], h2b[7];
#pragma unroll
        for (int j = 0; j < 7; j++) {
            const float2 t1 = *(const float2*)&s->h[(g*8+j)*HS2 + k0];
            const float2 t2 = *(const float2*)&s->h[(g*8+j)*HS2 + GH + k0];
            h1a[j] = t1.x; h1b[j] = t1.y;
            h2a[j] = t2.x; h2b[j] = t2.y;
        }
        const float* an = &s->adjn[g*49];
        const float* ai = &s->adji[g*49];

        const int mt = g >> 1;
        const int kt = k0 >> 4, c2 = (k0 & 15) >> 1;
        uint32_t* X = (uint32_t*)s->u.sX;
        const int base = (mt*KT + kt)*256;
        const int wsel = (g & 1) + 2*(c2 >> 2);

        float cs0 = 0.f, cs1 = 0.f;
#pragma unroll
        for (int i = 0; i < 7; i++) {
            float o1a = 0.f, o1b = 0.f, o2a = 0.f, o2b = 0.f;
#pragma unroll
            for (int j = 0; j < 7; j++) {
                const float wn = an[i*7 + j], wi = ai[i*7 + j];
                o1a = fmaf(wn, h1a[j], o1a); o1b = fmaf(wn, h1b[j], o1b);
                o2a = fmaf(wi, h2a[j], o2a); o2b = fmaf(wi, h2b[j], o2b);
            }
            const float x0 = 0.5f * (fmaxf(o1a, 0.f) + fmaxf(o2a, 0.f));
            const float x1 = 0.5f * (fmaxf(o1b, 0.f) + fmaxf(o2b, 0.f));

            if (!FINAL) {
                float hi0, lo0, hi1, lo1;
                hilo_h(x0, hi0, lo0); hilo_h(x1, hi1, lo1);
                const int l = i*4 + (c2 & 3);
                X[base + l*4 + wsel]       = pack_h(hi0, hi1);
                X[base + 128 + l*4 + wsel] = pack_h(lo0, lo1);
            } else {
                cs0 += x0; cs1 += x1;
            }
        }
        if (FINAL)
            atomicAdd(&s->gsum[g], cs0 * s->v[k0] + cs1 * s->v[k0+1]);
    }
    __syncthreads();   // sX/gsum complete before next phase
}

// ================= GEMM: sX (fp16 frags) x g_B[slot] -> sH ====================
// 2-term: D = Ah*Bh + Al*Bh  (= A * Bh; dropped A*Bl ~ 2^-12 relative)
__device__ void gemm(SM* s, int mt, int sl, int slot) {
    const int lane = threadIdx.x & 31;
    const uint2* __restrict__ Bp = (const uint2*)(g_B + (size_t)slot*BSLOT);
    const uint4* Xv = s->u.sX;

    float acc[NT][4];
#pragma unroll
    for (int t = 0; t < NT; t++)
#pragma unroll
        for (int q = 0; q < 4; q++) acc[t][q] = 0.f;

#pragma unroll 1
    for (int kt = 0; kt < KT; kt++) {
        const uint4 ah = Xv[(mt*KT + kt)*64 + lane];
        const uint4 al = Xv[(mt*KT + kt)*64 + 32 + lane];
#pragma unroll
        for (int nt = 0; nt < NT; nt++) {
            const uint2 b = Bp[(kt*NT + nt)*32 + lane];
            mma_f16(acc[nt], ah.x, ah.y, ah.z, ah.w, b.x, b.y);  // Ah*Bh
            mma_f16(acc[nt], al.x, al.y, al.z, al.w, b.x, b.y);  // Al*Bh
        }
    }

    const int r0 = mt*16 + (lane >> 2);
    const int c0 = sl*GH + (lane & 3)*2;
#pragma unroll
    for (int nt = 0; nt < NT; nt++) {
        *(float2*)&s->h[r0*HS2 + c0 + nt*8]     = make_float2(acc[nt][0], acc[nt][1]);
        *(float2*)&s->h[(r0+8)*HS2 + c0 + nt*8] = make_float2(acc[nt][2], acc[nt][3]);
    }
}

// ================= the fused kernel ===========================================
__global__ void __launch_bounds__(NTHR, 3)
k_fused(const float* __restrict__ ops, const float* __restrict__ adj,
        const float* __restrict__ nv,
        const float* __restrict__ w1_0, const float* __restrict__ w2_0,
        float* __restrict__ out) {
    extern __shared__ unsigned char smraw[];
    SM* s = (SM*)smraw;
    const int cta = blockIdx.x, tid = threadIdx.x;
    const int warp = tid >> 5, lane = tid & 31;
    const int mt = warp >> 1, sl = warp & 1;

    // ---- cooperative loads ----
    for (int q = tid; q < GPC*35; q += NTHR) s->u.l0.ops[q] = ops[(size_t)cta*GPC*35 + q];
    for (int q = tid; q < 720; q += NTHR) {
        s->u.l0.w0[q]       = w1_0[q];
        s->u.l0.w0[720 + q] = w2_0[q];
    }
    for (int q = tid; q < GH; q += NTHR)     s->v[q] = g_v[q];
    for (int q = tid; q < GPC*49; q += NTHR) s->adjraw[q] = adj[(size_t)cta*GPC*49 + q];
    if (tid < GPC) s->gsum[tid] = 0.f;
    __syncthreads();

    // ---- adjacency prep (one thread per graph) ----
    if (tid < GPC) prep_graph(s, tid);

    // ---- layer 0: h = ops @ W (K=5) ----
    {
        const int r0 = lane >> 2;          // 0..7 (7 = pad row)
        const int g0 = 2*mt, g1 = 2*mt + 1;
        const float* W = &s->u.l0.w0[sl*720];
        float o0[INH], o1[INH];
#pragma unroll
        for (int t = 0; t < INH; t++) {
            o0[t] = (r0 < 7) ? s->u.l0.ops[g0*35 + r0*5 + t] : 0.f;
            o1[t] = (r0 < 7) ? s->u.l0.ops[g1*35 + r0*5 + t] : 0.f;
        }
        const int rr = mt*16 + r0;
        const int cb = sl*GH + (lane & 3)*2;
#pragma unroll
        for (int nt = 0; nt < NT; nt++) {
            const int c = nt*8 + (lane & 3)*2;
            float h00 = 0.f, h01 = 0.f, h10 = 0.f, h11 = 0.f;
#pragma unroll
            for (int t = 0; t < INH; t++) {
                const float wa = W[t*GH + c], wb = W[t*GH + c + 1];
                h00 = fmaf(o0[t], wa, h00); h01 = fmaf(o0[t], wb, h01);
                h10 = fmaf(o1[t], wa, h10); h11 = fmaf(o1[t], wb, h11);
            }
            *(float2*)&s->h[rr*HS2 + cb + nt*8]     = make_float2(h00, h01);
            *(float2*)&s->h[(rr+8)*HS2 + cb + nt*8] = make_float2(h10, h11);
        }
    }
    mix<false>(s);              // L0 mix -> sX (X1 frags)

    gemm(s, mt, sl, 0 + sl);    // layer 1: slots {w1_1, w2_1}
    mix<false>(s);              // -> sX (X2 frags)

    gemm(s, mt, sl, 2 + sl);    // layer 2: slots {w1_2, w2_2}
    mix<true>(s);               // -> gsum (pool . v)

    if (tid < GPC) {
        const int b = cta*GPC + tid;
        out[b] = s->gsum[tid] / nv[b];
    }
}

// ================= launch ======================================================
extern "C" void kernel_launch(void* const* d_in, const int* in_sizes, int n_in,
                              void* d_out, int out_size) {
    const float* ops  = (const float*)d_in[0];
    const float* adj  = (const float*)d_in[1];
    const float* nv   = (const float*)d_in[2];
    const float* w1_0 = (const float*)d_in[3];
    const float* w2_0 = (const float*)d_in[4];
    const float* w1_1 = (const float*)d_in[5];
    const float* w2_1 = (const float*)d_in[6];
    const float* w1_2 = (const float*)d_in[7];
    const float* w2_2 = (const float*)d_in[8];
    const float* fc1  = (const float*)d_in[9];
    const float* fc2  = (const float*)d_in[10];
    float* out = (float*)d_out;

    static int configured = 0;
    if (!configured) {
        cudaFuncSetAttribute(k_fused, cudaFuncAttributeMaxDynamicSharedMemorySize, SMEMB);
        configured = 1;
    }

    k_prep <<<5, 256>>>(w1_1, w2_1, w1_2, w2_2, fc1, fc2);
    k_fused<<<NCTA, NTHR, SMEMB>>>(ops, adj, nv, w1_0, w2_0, out);
}

// round 11
// speedup vs baseline: 2.0472x; 1.2502x over previous
#include <cuda_runtime.h>
#include <cuda_fp16.h>
#include <cstdint>

// ---------------- problem constants ----------------
#define NB     65536
#define GS     7
#define INH    5
#define GH     144
#define LINH   128
#define GPC    4              // graphs per CTA (padded to 8 rows each)
#define NCTA   (NB/GPC)       // 16384
#define NTHR   128            // 4 warps: (mtile 0..1) x (slot 0..1)
#define KT     9              // 144/16 k-tiles
#define NT     18             // 144/8 n-tiles (full N per warp)
#define HS2    290            // sH row stride (floats)
#define BBLK   256            // bytes per (ktile,ntile) B frag block
#define BSLOT  (KT*NT*BBLK)   // 41472 bytes per weight slot

// ---------------- device scratch ----------------
__device__ unsigned char g_B[4*BSLOT];   // frag-packed fp16 weights
__device__ float g_v[GH];                // fused fc vector

// ---------------- helpers ----------------
__device__ __forceinline__ uint32_t pack_h(float a, float b) {
    __half2 t = __floats2half2_rn(a, b);   // a in low half
    return *(uint32_t*)&t;
}
__device__ __forceinline__ void mma_f16(float* c, uint32_t a0, uint32_t a1,
                                        uint32_t a2, uint32_t a3,
                                        uint32_t b0, uint32_t b1) {
    asm volatile(
        "mma.sync.aligned.m16n8k16.row.col.f32.f16.f16.f32 "
        "{%0,%1,%2,%3}, {%4,%5,%6,%7}, {%8,%9}, {%0,%1,%2,%3};"
        : "+f"(c[0]), "+f"(c[1]), "+f"(c[2]), "+f"(c[3])
        : "r"(a0), "r"(a1), "r"(a2), "r"(a3), "r"(b0), "r"(b1));
}

// ---------------- shared memory ----------------
struct SM {
    union {
        uint4 sX[2*KT*32];      // 9216 B: frag-packed fp16 X (2 mtiles)
        struct { float ops[GPC*35]; float w0[2*720]; } l0;
    } u;
    float h[32*HS2];            // 37120 B: 32 rows x [h1(144) | h2(144)] fp32
    float adjn[GPC*49];
    float adji[GPC*49];
    float adjraw[GPC*49];
    float v[GH];
    float gsum[GPC];
};
#define SMEMB ((int)sizeof(SM))   // ~49.3 KB -> 4 CTAs/SM

// ================= prep kernel: blocks 0-3 pack B, block 4 builds v ===========
// slot order: 0=w1_1 1=w2_1 2=w1_2 3=w2_2.
__global__ void k_prep(const float* __restrict__ wa, const float* __restrict__ wb,
                       const float* __restrict__ wc, const float* __restrict__ wd,
                       const float* __restrict__ fc1, const float* __restrict__ fc2) {
    if (blockIdx.x == 4) {
        const int k = threadIdx.x;
        if (k < GH) {
            float s = 0.f;
            for (int j = 0; j < LINH; j++) s = fmaf(fc2[j], fc1[j*GH + k], s);
            g_v[k] = s;
        }
        return;
    }
    const float* W = blockIdx.x == 0 ? wa : blockIdx.x == 1 ? wb
                   : blockIdx.x == 2 ? wc : wd;
    unsigned char* out = g_B + (size_t)blockIdx.x * BSLOT;
    for (int f = threadIdx.x; f < KT*NT*32; f += 256) {
        const int kt = f / (NT*32);
        const int nt = (f / 32) % NT;
        const int l  = f & 31;
        const int n  = nt*8 + (l >> 2);
        const int kb = kt*16 + (l & 3)*2;
        uint2 v;
        v.x = pack_h(W[(kb+0)*GH + n], W[(kb+1)*GH + n]);
        v.y = pack_h(W[(kb+8)*GH + n], W[(kb+9)*GH + n]);
        *(uint2*)(out + (size_t)(kt*NT + nt)*BBLK + l*8) = v;
    }
}

// ================= per-graph adjacency prep ====================================
__device__ void prep_graph(SM* s, int g) {
    float a[49];
#pragma unroll
    for (int i = 0; i < 49; i++) a[i] = s->adjraw[g*49 + i];
#pragma unroll
    for (int i = 0; i < 7; i++) {
        a[i*7 + i] += 1.0f;
        float rs = 0.f;
#pragma unroll
        for (int j = 0; j < 7; j++) rs += a[i*7 + j];
        const float inv = 1.0f / rs;
#pragma unroll
        for (int j = 0; j < 7; j++) a[i*7 + j] *= inv;
    }
#pragma unroll
    for (int i = 0; i < 7; i++) {
        float rs = 0.f;
#pragma unroll
        for (int j = 0; j < 7; j++) rs += a[i*7 + j];
        const float inv = 1.0f / rs;
#pragma unroll
        for (int j = 0; j < 7; j++) s->adjn[g*49 + i*7 + j] = a[i*7 + j] * inv;
    }
#pragma unroll
    for (int i = 0; i < 7; i++) {
        float cs = 0.f;
#pragma unroll
        for (int r = 0; r < 7; r++) cs += a[r*7 + i];
        const float inv = 1.0f / cs;
#pragma unroll
        for (int j = 0; j < 7; j++) s->adji[g*49 + i*7 + j] = a[j*7 + i] * inv;
    }
}

// ================= mix: sH -> (sX frags | pooled gsum) ========================
template <bool FINAL>
__device__ void mix(SM* s) {
    const int tid = threadIdx.x;
    __syncthreads();   // sH complete; prior sX reads done

    for (int item = tid; item < GPC*72; item += NTHR) {
        const int g  = item / 72;
        const int kp = item - g*72;
        const int k0 = kp*2;

        float h1a[7], h1b[7], h2a[7], h2b[7];
#pragma unroll
        for (int j = 0; j < 7; j++) {
            const float2 t1 = *(const float2*)&s->h[(g*8+j)*HS2 + k0];
            const float2 t2 = *(const float2*)&s->h[(g*8+j)*HS2 + GH + k0];
            h1a[j] = t1.x; h1b[j] = t1.y;
            h2a[j] = t2.x; h2b[j] = t2.y;
        }
        const float* an = &s->adjn[g*49];
        const float* ai = &s->adji[g*49];

        const int mt = g >> 1;
        const int kt = k0 >> 4, c2 = (k0 & 15) >> 1;
        uint32_t* X = (uint32_t*)s->u.sX;
        const int base = (mt*KT + kt)*128;
        const int wsel = (g & 1) + 2*(c2 >> 2);

        float cs0 = 0.f, cs1 = 0.f;
#pragma unroll
        for (int i = 0; i < 7; i++) {
            float o1a = 0.f, o1b = 0.f, o2a = 0.f, o2b = 0.f;
#pragma unroll
            for (int j = 0; j < 7; j++) {
                const float wn = an[i*7 + j], wi = ai[i*7 + j];
                o1a = fmaf(wn, h1a[j], o1a); o1b = fmaf(wn, h1b[j], o1b);
                o2a = fmaf(wi, h2a[j], o2a); o2b = fmaf(wi, h2b[j], o2b);
            }
            const float x0 = 0.5f * (fmaxf(o1a, 0.f) + fmaxf(o2a, 0.f));
            const float x1 = 0.5f * (fmaxf(o1b, 0.f) + fmaxf(o2b, 0.f));

            if (!FINAL) {
                const int l = i*4 + (c2 & 3);
                X[base + l*4 + wsel] = pack_h(x0, x1);   // single fp16 frag
            } else {
                cs0 += x0; cs1 += x1;
            }
        }
        if (FINAL)
            atomicAdd(&s->gsum[g], cs0 * s->v[k0] + cs1 * s->v[k0+1]);
    }
    __syncthreads();   // sX/gsum complete before next phase
}

// ================= GEMM: sX (fp16 frags) x g_B[slot] -> sH ====================
// single-term: D = A(fp16) * B(fp16), fp32 accumulate
__device__ void gemm(SM* s, int mt, int sl, int slot) {
    const int lane = threadIdx.x & 31;
    const uint2* __restrict__ Bp = (const uint2*)(g_B + (size_t)slot*BSLOT);
    const uint4* Xv = s->u.sX;

    float acc[NT][4];
#pragma unroll
    for (int t = 0; t < NT; t++)
#pragma unroll
        for (int q = 0; q < 4; q++) acc[t][q] = 0.f;

#pragma unroll 1
    for (int kt = 0; kt < KT; kt++) {
        const uint4 a = Xv[(mt*KT + kt)*32 + lane];
#pragma unroll
        for (int nt = 0; nt < NT; nt++) {
            const uint2 b = Bp[(kt*NT + nt)*32 + lane];
            mma_f16(acc[nt], a.x, a.y, a.z, a.w, b.x, b.y);
        }
    }

    const int r0 = mt*16 + (lane >> 2);
    const int c0 = sl*GH + (lane & 3)*2;
#pragma unroll
    for (int nt = 0; nt < NT; nt++) {
        *(float2*)&s->h[r0*HS2 + c0 + nt*8]     = make_float2(acc[nt][0], acc[nt][1]);
        *(float2*)&s->h[(r0+8)*HS2 + c0 + nt*8] = make_float2(acc[nt][2], acc[nt][3]);
    }
}

// ================= the fused kernel ===========================================
__global__ void __launch_bounds__(NTHR, 4)
k_fused(const float* __restrict__ ops, const float* __restrict__ adj,
        const float* __restrict__ nv,
        const float* __restrict__ w1_0, const float* __restrict__ w2_0,
        float* __restrict__ out) {
    extern __shared__ unsigned char smraw[];
    SM* s = (SM*)smraw;
    const int cta = blockIdx.x, tid = threadIdx.x;
    const int warp = tid >> 5, lane = tid & 31;
    const int mt = warp >> 1, sl = warp & 1;

    // ---- cooperative loads ----
    for (int q = tid; q < GPC*35; q += NTHR) s->u.l0.ops[q] = ops[(size_t)cta*GPC*35 + q];
    for (int q = tid; q < 720; q += NTHR) {
        s->u.l0.w0[q]       = w1_0[q];
        s->u.l0.w0[720 + q] = w2_0[q];
    }
    for (int q = tid; q < GH; q += NTHR)     s->v[q] = g_v[q];
    for (int q = tid; q < GPC*49; q += NTHR) s->adjraw[q] = adj[(size_t)cta*GPC*49 + q];
    if (tid < GPC) s->gsum[tid] = 0.f;
    __syncthreads();

    // ---- adjacency prep (one thread per graph) ----
    if (tid < GPC) prep_graph(s, tid);

    // ---- layer 0: h = ops @ W (K=5) ----
    {
        const int r0 = lane >> 2;          // 0..7 (7 = pad row)
        const int g0 = 2*mt, g1 = 2*mt + 1;
        const float* W = &s->u.l0.w0[sl*720];
        float o0[INH], o1[INH];
#pragma unroll
        for (int t = 0; t < INH; t++) {
            o0[t] = (r0 < 7) ? s->u.l0.ops[g0*35 + r0*5 + t] : 0.f;
            o1[t] = (r0 < 7) ? s->u.l0.ops[g1*35 + r0*5 + t] : 0.f;
        }
        const int rr = mt*16 + r0;
        const int cb = sl*GH + (lane & 3)*2;
#pragma unroll
        for (int nt = 0; nt < NT; nt++) {
            const int c = nt*8 + (lane & 3)*2;
            float h00 = 0.f, h01 = 0.f, h10 = 0.f, h11 = 0.f;
#pragma unroll
            for (int t = 0; t < INH; t++) {
                const float wa = W[t*GH + c], wb = W[t*GH + c + 1];
                h00 = fmaf(o0[t], wa, h00); h01 = fmaf(o0[t], wb, h01);
                h10 = fmaf(o1[t], wa, h10); h11 = fmaf(o1[t], wb, h11);
            }
            *(float2*)&s->h[rr*HS2 + cb + nt*8]     = make_float2(h00, h01);
            *(float2*)&s->h[(rr+8)*HS2 + cb + nt*8] = make_float2(h10, h11);
        }
    }
    mix<false>(s);              // L0 mix -> sX (X1 frags)

    gemm(s, mt, sl, 0 + sl);    // layer 1: slots {w1_1, w2_1}
    mix<false>(s);              // -> sX (X2 frags)

    gemm(s, mt, sl, 2 + sl);    // layer 2: slots {w1_2, w2_2}
    mix<true>(s);               // -> gsum (pool . v)

    if (tid < GPC) {
        const int b = cta*GPC + tid;
        out[b] = s->gsum[tid] / nv[b];
    }
}

// ================= launch ======================================================
extern "C" void kernel_launch(void* const* d_in, const int* in_sizes, int n_in,
                              void* d_out, int out_size) {
    const float* ops  = (const float*)d_in[0];
    const float* adj  = (const float*)d_in[1];
    const float* nv   = (const float*)d_in[2];
    const float* w1_0 = (const float*)d_in[3];
    const float* w2_0 = (const float*)d_in[4];
    const float* w1_1 = (const float*)d_in[5];
    const float* w2_1 = (const float*)d_in[6];
    const float* w1_2 = (const float*)d_in[7];
    const float* w2_2 = (const float*)d_in[8];
    const float* fc1  = (const float*)d_in[9];
    const float* fc2  = (const float*)d_in[10];
    float* out = (float*)d_out;

    static int configured = 0;
    if (!configured) {
        cudaFuncSetAttribute(k_fused, cudaFuncAttributeMaxDynamicSharedMemorySize, SMEMB);
        configured = 1;
    }

    k_prep <<<5, 256>>>(w1_1, w2_1, w1_2, w2_2, fc1, fc2);
    k_fused<<<NCTA, NTHR, SMEMB>>>(ops, adj, nv, w1_0, w2_0, out);
}

// round 12
// speedup vs baseline: 2.3988x; 1.1718x over previous
#include <cuda_runtime.h>
#include <cuda_fp16.h>
#include <cstdint>

// ---------------- problem constants ----------------
#define NB     65536
#define GS     7
#define INH    5
#define GH     144
#define LINH   128
#define GPC    4              // graphs per CTA (padded to 8 rows each)
#define NCTA   (NB/GPC)       // 16384
#define NTHR   128            // 4 warps: (mtile 0..1) x (slot 0..1)
#define KT     9              // 144/16 k-tiles
#define NT     18             // 144/8 n-tiles (full N per warp)
#define NTP    9              // nt-pairs
#define HS2    296            // sH row stride (floats); 296 % 32 == 8 -> conflict-free stores
#define BSLOT  (KT*NT*256)    // 41472 bytes per weight slot

// ---------------- device scratch ----------------
__device__ unsigned char g_B[4*BSLOT];   // frag-packed fp16 weights (paired-nt uint4)
__device__ float g_v[GH];                // fused fc vector

// ---------------- helpers ----------------
__device__ __forceinline__ uint32_t pack_h(float a, float b) {
    __half2 t = __floats2half2_rn(a, b);   // a in low half
    return *(uint32_t*)&t;
}
__device__ __forceinline__ void mma_f16(float* c, uint32_t a0, uint32_t a1,
                                        uint32_t a2, uint32_t a3,
                                        uint32_t b0, uint32_t b1) {
    asm volatile(
        "mma.sync.aligned.m16n8k16.row.col.f32.f16.f16.f32 "
        "{%0,%1,%2,%3}, {%4,%5,%6,%7}, {%8,%9}, {%0,%1,%2,%3};"
        : "+f"(c[0]), "+f"(c[1]), "+f"(c[2]), "+f"(c[3])
        : "r"(a0), "r"(a1), "r"(a2), "r"(a3), "r"(b0), "r"(b1));
}

// ---------------- shared memory ----------------
struct SM {
    union {
        uint4 sX[2*KT*32];      // 9216 B: frag-packed fp16 X (2 mtiles)
        struct { float ops[GPC*35]; float w0[2*720]; } l0;
    } u;
    float h[32*HS2];            // 37888 B: 32 rows x [h1(144) | h2(144)] fp32
    float adjn[GPC*49];
    float adji[GPC*49];
    float adjraw[GPC*49];
    float v[GH];
    float gsum[GPC];
};
#define SMEMB ((int)sizeof(SM))   // ~50 KB -> 4 CTAs/SM

// ================= prep kernel: blocks 0-3 pack B, block 4 builds v ===========
// slot order: 0=w1_1 1=w2_1 2=w1_2 3=w2_2.
// B layout: block (kt, ntp) of 512 B; lane l holds 16 B = [nt=2ntp uint2][nt=2ntp+1 uint2]
__global__ void k_prep(const float* __restrict__ wa, const float* __restrict__ wb,
                       const float* __restrict__ wc, const float* __restrict__ wd,
                       const float* __restrict__ fc1, const float* __restrict__ fc2) {
    if (blockIdx.x == 4) {
        const int k = threadIdx.x;
        if (k < GH) {
            float s = 0.f;
            for (int j = 0; j < LINH; j++) s = fmaf(fc2[j], fc1[j*GH + k], s);
            g_v[k] = s;
        }
        return;
    }
    const float* W = blockIdx.x == 0 ? wa : blockIdx.x == 1 ? wb
                   : blockIdx.x == 2 ? wc : wd;
    unsigned char* out = g_B + (size_t)blockIdx.x * BSLOT;
    for (int f = threadIdx.x; f < KT*NT*32; f += 256) {
        const int kt = f / (NT*32);
        const int nt = (f / 32) % NT;
        const int l  = f & 31;
        const int n  = nt*8 + (l >> 2);
        const int kb = kt*16 + (l & 3)*2;
        uint2 v;
        v.x = pack_h(W[(kb+0)*GH + n], W[(kb+1)*GH + n]);
        v.y = pack_h(W[(kb+8)*GH + n], W[(kb+9)*GH + n]);
        *(uint2*)(out + (size_t)(kt*NTP + (nt >> 1))*512 + l*16 + (nt & 1)*8) = v;
    }
}

// ================= per-graph adjacency prep ====================================
__device__ void prep_graph(SM* s, int g) {
    float a[49];
#pragma unroll
    for (int i = 0; i < 49; i++) a[i] = s->adjraw[g*49 + i];
#pragma unroll
    for (int i = 0; i < 7; i++) {
        a[i*7 + i] += 1.0f;
        float rs = 0.f;
#pragma unroll
        for (int j = 0; j < 7; j++) rs += a[i*7 + j];
        const float inv = 1.0f / rs;
#pragma unroll
        for (int j = 0; j < 7; j++) a[i*7 + j] *= inv;
    }
#pragma unroll
    for (int i = 0; i < 7; i++) {
        float rs = 0.f;
#pragma unroll
        for (int j = 0; j < 7; j++) rs += a[i*7 + j];
        const float inv = 1.0f / rs;
#pragma unroll
        for (int j = 0; j < 7; j++) s->adjn[g*49 + i*7 + j] = a[i*7 + j] * inv;
    }
#pragma unroll
    for (int i = 0; i < 7; i++) {
        float cs = 0.f;
#pragma unroll
        for (int r = 0; r < 7; r++) cs += a[r*7 + i];
        const float inv = 1.0f / cs;
#pragma unroll
        for (int j = 0; j < 7; j++) s->adji[g*49 + i*7 + j] = a[j*7 + i] * inv;
    }
}

// ================= mix: sH -> (sX frags | pooled gsum) ========================
template <bool FINAL>
__device__ void mix(SM* s) {
    const int tid = threadIdx.x;
    __syncthreads();   // sH complete; prior sX reads done

    for (int item = tid; item < GPC*72; item += NTHR) {
        const int g  = item / 72;
        const int kp = item - g*72;
        const int k0 = kp*2;

        float h1a[7], h1b[7], h2a[7], h2b[7];
#pragma unroll
        for (int j = 0; j < 7; j++) {
            const float2 t1 = *(const float2*)&s->h[(g*8+j)*HS2 + k0];
            const float2 t2 = *(const float2*)&s->h[(g*8+j)*HS2 + GH + k0];
            h1a[j] = t1.x; h1b[j] = t1.y;
            h2a[j] = t2.x; h2b[j] = t2.y;
        }
        const float* an = &s->adjn[g*49];
        const float* ai = &s->adji[g*49];

        const int mt = g >> 1;
        const int kt = k0 >> 4, c2 = (k0 & 15) >> 1;
        uint32_t* X = (uint32_t*)s->u.sX;
        const int base = (mt*KT + kt)*128;
        const int wsel = (g & 1) + 2*(c2 >> 2);

        float cs0 = 0.f, cs1 = 0.f;
#pragma unroll
        for (int i = 0; i < 7; i++) {
            float o1a = 0.f, o1b = 0.f, o2a = 0.f, o2b = 0.f;
#pragma unroll
            for (int j = 0; j < 7; j++) {
                const float wn = an[i*7 + j], wi = ai[i*7 + j];
                o1a = fmaf(wn, h1a[j], o1a); o1b = fmaf(wn, h1b[j], o1b);
                o2a = fmaf(wi, h2a[j], o2a); o2b = fmaf(wi, h2b[j], o2b);
            }
            const float x0 = 0.5f * (fmaxf(o1a, 0.f) + fmaxf(o2a, 0.f));
            const float x1 = 0.5f * (fmaxf(o1b, 0.f) + fmaxf(o2b, 0.f));

            if (!FINAL) {
                const int l = i*4 + (c2 & 3);
                X[base + l*4 + wsel] = pack_h(x0, x1);   // single fp16 frag
            } else {
                cs0 += x0; cs1 += x1;
            }
        }
        if (FINAL)
            atomicAdd(&s->gsum[g], cs0 * s->v[k0] + cs1 * s->v[k0+1]);
    }
    __syncthreads();   // sX/gsum complete before next phase
}

// ================= GEMM: sX (fp16 frags) x g_B[slot] -> sH ====================
// single-term: D = A(fp16) * B(fp16), fp32 accumulate; B loaded as paired-nt uint4
__device__ void gemm(SM* s, int mt, int sl, int slot) {
    const int lane = threadIdx.x & 31;
    const uint4* __restrict__ Bp = (const uint4*)(g_B + (size_t)slot*BSLOT);
    const uint4* Xv = s->u.sX;

    float acc[NT][4];
#pragma unroll
    for (int t = 0; t < NT; t++)
#pragma unroll
        for (int q = 0; q < 4; q++) acc[t][q] = 0.f;

#pragma unroll 1
    for (int kt = 0; kt < KT; kt++) {
        const uint4 a = Xv[(mt*KT + kt)*32 + lane];
#pragma unroll
        for (int ntp = 0; ntp < NTP; ntp++) {
            const uint4 b = Bp[(kt*NTP + ntp)*32 + lane];
            mma_f16(acc[2*ntp],     a.x, a.y, a.z, a.w, b.x, b.y);
            mma_f16(acc[2*ntp + 1], a.x, a.y, a.z, a.w, b.z, b.w);
        }
    }

    const int r0 = mt*16 + (lane >> 2);
    const int c0 = sl*GH + (lane & 3)*2;
#pragma unroll
    for (int nt = 0; nt < NT; nt++) {
        *(float2*)&s->h[r0*HS2 + c0 + nt*8]     = make_float2(acc[nt][0], acc[nt][1]);
        *(float2*)&s->h[(r0+8)*HS2 + c0 + nt*8] = make_float2(acc[nt][2], acc[nt][3]);
    }
}

// ================= the fused kernel ===========================================
__global__ void __launch_bounds__(NTHR, 4)
k_fused(const float* __restrict__ ops, const float* __restrict__ adj,
        const float* __restrict__ nv,
        const float* __restrict__ w1_0, const float* __restrict__ w2_0,
        float* __restrict__ out) {
    extern __shared__ unsigned char smraw[];
    SM* s = (SM*)smraw;
    const int cta = blockIdx.x, tid = threadIdx.x;
    const int warp = tid >> 5, lane = tid & 31;
    const int mt = warp >> 1, sl = warp & 1;

    // ---- cooperative loads ----
    for (int q = tid; q < GPC*35; q += NTHR) s->u.l0.ops[q] = ops[(size_t)cta*GPC*35 + q];
    for (int q = tid; q < 720; q += NTHR) {
        s->u.l0.w0[q]       = w1_0[q];
        s->u.l0.w0[720 + q] = w2_0[q];
    }
    for (int q = tid; q < GH; q += NTHR)     s->v[q] = g_v[q];
    for (int q = tid; q < GPC*49; q += NTHR) s->adjraw[q] = adj[(size_t)cta*GPC*49 + q];
    if (tid < GPC) s->gsum[tid] = 0.f;
    __syncthreads();

    // ---- adjacency prep (one thread per graph) ----
    if (tid < GPC) prep_graph(s, tid);

    // ---- layer 0: h = ops @ W (K=5) ----
    {
        const int r0 = lane >> 2;          // 0..7 (7 = pad row)
        const int g0 = 2*mt, g1 = 2*mt + 1;
        const float* W = &s->u.l0.w0[sl*720];
        float o0[INH], o1[INH];
#pragma unroll
        for (int t = 0; t < INH; t++) {
            o0[t] = (r0 < 7) ? s->u.l0.ops[g0*35 + r0*5 + t] : 0.f;
            o1[t] = (r0 < 7) ? s->u.l0.ops[g1*35 + r0*5 + t] : 0.f;
        }
        const int rr = mt*16 + r0;
        const int cb = sl*GH + (lane & 3)*2;
#pragma unroll
        for (int nt = 0; nt < NT; nt++) {
            const int c = nt*8 + (lane & 3)*2;
            float h00 = 0.f, h01 = 0.f, h10 = 0.f, h11 = 0.f;
#pragma unroll
            for (int t = 0; t < INH; t++) {
                const float wa = W[t*GH + c], wb = W[t*GH + c + 1];
                h00 = fmaf(o0[t], wa, h00); h01 = fmaf(o0[t], wb, h01);
                h10 = fmaf(o1[t], wa, h10); h11 = fmaf(o1[t], wb, h11);
            }
            *(float2*)&s->h[rr*HS2 + cb + nt*8]     = make_float2(h00, h01);
            *(float2*)&s->h[(rr+8)*HS2 + cb + nt*8] = make_float2(h10, h11);
        }
    }
    mix<false>(s);              // L0 mix -> sX (X1 frags)

    gemm(s, mt, sl, 0 + sl);    // layer 1: slots {w1_1, w2_1}
    mix<false>(s);              // -> sX (X2 frags)

    gemm(s, mt, sl, 2 + sl);    // layer 2: slots {w1_2, w2_2}
    mix<true>(s);               // -> gsum (pool . v)

    if (tid < GPC) {
        const int b = cta*GPC + tid;
        out[b] = s->gsum[tid] / nv[b];
    }
}

// ================= launch ======================================================
extern "C" void kernel_launch(void* const* d_in, const int* in_sizes, int n_in,
                              void* d_out, int out_size) {
    const float* ops  = (const float*)d_in[0];
    const float* adj  = (const float*)d_in[1];
    const float* nv   = (const float*)d_in[2];
    const float* w1_0 = (const float*)d_in[3];
    const float* w2_0 = (const float*)d_in[4];
    const float* w1_1 = (const float*)d_in[5];
    const float* w2_1 = (const float*)d_in[6];
    const float* w1_2 = (const float*)d_in[7];
    const float* w2_2 = (const float*)d_in[8];
    const float* fc1  = (const float*)d_in[9];
    const float* fc2  = (const float*)d_in[10];
    float* out = (float*)d_out;

    static int configured = 0;
    if (!configured) {
        cudaFuncSetAttribute(k_fused, cudaFuncAttributeMaxDynamicSharedMemorySize, SMEMB);
        configured = 1;
    }

    k_prep <<<5, 256>>>(w1_1, w2_1, w1_2, w2_2, fc1, fc2);
    k_fused<<<NCTA, NTHR, SMEMB>>>(ops, adj, nv, w1_0, w2_0, out);
}